// round 5
// baseline (speedup 1.0000x reference)
#include <cuda_runtime.h>
#include <math.h>
#include <float.h>

// Divisive normalization over time.
// Reference:
//   y1[t] = sum_{s<t} x[s]*(t-1-s)*a1^(t-1-s)   (recurrence A,Bm)
//   drive = y1 / max_t y1
//   y2[t] = sum_{s<t} drive[s]*a2^(t-1-s)
//   norm  = y2 / max_t y2
//   r[t]  = nan_to_num(|drive^n| / (|norm^n| + sigma)); output r[t_sel]
//
// Algebra: y2 = conv(y1,a2)/max(y1) and the max(y1) cancels in norm:
//   norm[t] = z2[t]/max_t z2 with z2 = conv(y1, a2).
// (scan outputs include y1[0]=0 so max_t y1 >= 0 — no sign flip possible.)
// => single streaming pass over x, per-pixel register recurrences.

__global__ __launch_bounds__(128) void divnorm_kernel(
    const float* __restrict__ x,      // (T, P)
    const float* __restrict__ tau1,   // (CWH)
    const float* __restrict__ tau2,   // (CWH)
    const float* __restrict__ sigma,  // (CWH)
    const float* __restrict__ nexp,   // (CWH)
    const int*   __restrict__ t_sel,  // scalar
    float*       __restrict__ out,    // (P)
    int P4, int T, int CWH)
{
    int tid = blockIdx.x * blockDim.x + threadIdx.x;
    if (tid >= P4) return;
    const int p   = tid * 4;
    const int cwh = p % CWH;              // CWH % 4 == 0: group never crosses batch boundary
    const int tt  = *t_sel;

    const float4 t1 = *reinterpret_cast<const float4*>(tau1 + cwh);
    const float4 t2 = *reinterpret_cast<const float4*>(tau2 + cwh);

    float a1[4], a2[4];
    a1[0] = expf(-1.0f / t1.x); a1[1] = expf(-1.0f / t1.y);
    a1[2] = expf(-1.0f / t1.z); a1[3] = expf(-1.0f / t1.w);
    a2[0] = expf(-1.0f / t2.x); a2[1] = expf(-1.0f / t2.y);
    a2[2] = expf(-1.0f / t2.z); a2[3] = expf(-1.0f / t2.w);

    float A[4], Bm[4], c[4], my1[4], mz2[4], y1s[4], z2s[4];
#pragma unroll
    for (int i = 0; i < 4; ++i) {
        A[i] = 0.0f; Bm[i] = 0.0f; c[i] = 0.0f;
        my1[i] = -FLT_MAX; mz2[i] = -FLT_MAX;
        y1s[i] = 0.0f; z2s[i] = 0.0f;
    }

    const float4* __restrict__ x4 = reinterpret_cast<const float4*>(x);

#pragma unroll 4
    for (int t = 0; t < T; ++t) {
        float4 xv = __ldg(&x4[(size_t)t * P4 + tid]);
        float xs[4] = {xv.x, xv.y, xv.z, xv.w};
        const bool sel = (t == tt);
#pragma unroll
        for (int i = 0; i < 4; ++i) {
            const float y1 = Bm[i];                  // scan output at t
            const float z2 = c[i];                   // scan output at t
            const float nA = fmaf(a1[i], A[i], xs[i]);
            const float nB = a1[i] * (Bm[i] + A[i]); // uses OLD A
            c[i]   = fmaf(a2[i], c[i], y1);          // z2 recurrence driven by y1[t]
            my1[i] = fmaxf(my1[i], y1);
            mz2[i] = fmaxf(mz2[i], z2);
            if (sel) { y1s[i] = y1; z2s[i] = z2; }
            A[i] = nA; Bm[i] = nB;
        }
    }

    const float4 sg = *reinterpret_cast<const float4*>(sigma + cwh);
    const float4 nv = *reinterpret_cast<const float4*>(nexp + cwh);
    const float sgs[4] = {sg.x, sg.y, sg.z, sg.w};
    const float nvs[4] = {nv.x, nv.y, nv.z, nv.w};

    float4 ov;
    float* ovp = reinterpret_cast<float*>(&ov);
#pragma unroll
    for (int i = 0; i < 4; ++i) {
        const float drive = y1s[i] / my1[i];
        const float nrm   = z2s[i] / mz2[i];
        const float id    = fabsf(powf(drive, nvs[i]));
        const float nr    = fabsf(powf(nrm,  nvs[i])) + sgs[i];
        float r = id / nr;
        // nan_to_num semantics
        if (isnan(r))      r = 0.0f;
        else if (isinf(r)) r = (r > 0.0f) ? FLT_MAX : -FLT_MAX;
        ovp[i] = r;
    }
    *reinterpret_cast<float4*>(out + p) = ov;
}

extern "C" void kernel_launch(void* const* d_in, const int* in_sizes, int n_in,
                              void* d_out, int out_size)
{
    const float* x     = (const float*)d_in[0];
    const float* tau1  = (const float*)d_in[1];
    const float* tau2  = (const float*)d_in[2];
    const float* sigma = (const float*)d_in[3];
    const float* nexp  = (const float*)d_in[4];
    const int*   t_sel = (const int*)  d_in[5];
    float* out = (float*)d_out;

    const int P   = out_size;               // B*C*W*H = 262144
    const int T   = in_sizes[0] / P;        // 128
    const int CWH = in_sizes[3];            // 32768
    const int P4  = P / 4;

    const int threads = 128;
    const int blocks  = (P4 + threads - 1) / threads;
    divnorm_kernel<<<blocks, threads>>>(x, tau1, tau2, sigma, nexp, t_sel, out,
                                        P4, T, CWH);
}